// round 1
// baseline (speedup 1.0000x reference)
#include <cuda_runtime.h>

// Problem constants: B=2, T=2048, C=1024, H=16, D=64
// qkv scratch: [B*T, 3C] = 4096 x 3072 floats
// attn scratch: [B*T, C]  = 4096 x 1024 floats
__device__ float g_qkv[4096 * 3072];
__device__ float g_attn[4096 * 1024];

// ---------------------------------------------------------------------------
// Classic 128x128x8 SGEMM with bias epilogue. C = A(MxK) * B(KxN) + bias(N)
// A, B, C row-major. M%128==0, N%128==0, K%8==0 assumed.
// 256 threads, each computes an 8x8 fragment.
// ---------------------------------------------------------------------------
__global__ __launch_bounds__(256, 2)
void sgemm_bias_kernel(const float* __restrict__ A, const float* __restrict__ B,
                       const float* __restrict__ bias, float* __restrict__ Cmat,
                       int M, int N, int K)
{
    __shared__ float As[8][128];
    __shared__ float Bs[8][128];

    const int tid = threadIdx.x;
    const int tx  = tid & 15;
    const int ty  = tid >> 4;
    const int row0 = blockIdx.y * 128;
    const int col0 = blockIdx.x * 128;

    // Load mapping: A tile 128x8 (1 float4/thread), B tile 8x128 (1 float4/thread)
    const int arow = tid >> 1;        // 0..127
    const int acol = (tid & 1) * 4;   // 0 or 4
    const int brow = tid >> 5;        // 0..7
    const int bcol = (tid & 31) * 4;  // 0..124

    const float* Aptr = A + (size_t)(row0 + arow) * K + acol;
    const float* Bptr = B + (size_t)brow * N + col0 + bcol;

    float acc[8][8];
#pragma unroll
    for (int i = 0; i < 8; i++)
#pragma unroll
        for (int j = 0; j < 8; j++) acc[i][j] = 0.0f;

    for (int k0 = 0; k0 < K; k0 += 8) {
        float4 av = *(const float4*)(Aptr + k0);
        float4 bv = *(const float4*)(Bptr + (size_t)k0 * N);
        As[acol + 0][arow] = av.x;
        As[acol + 1][arow] = av.y;
        As[acol + 2][arow] = av.z;
        As[acol + 3][arow] = av.w;
        *(float4*)&Bs[brow][bcol] = bv;
        __syncthreads();

#pragma unroll
        for (int kk = 0; kk < 8; kk++) {
            float a[8], b[8];
            *(float4*)&a[0] = *(const float4*)&As[kk][ty * 8];
            *(float4*)&a[4] = *(const float4*)&As[kk][ty * 8 + 4];
            *(float4*)&b[0] = *(const float4*)&Bs[kk][tx * 8];
            *(float4*)&b[4] = *(const float4*)&Bs[kk][tx * 8 + 4];
#pragma unroll
            for (int i = 0; i < 8; i++)
#pragma unroll
                for (int j = 0; j < 8; j++)
                    acc[i][j] += a[i] * b[j];
        }
        __syncthreads();
    }

#pragma unroll
    for (int i = 0; i < 8; i++) {
        float* crow = Cmat + (size_t)(row0 + ty * 8 + i) * N + col0 + tx * 8;
#pragma unroll
        for (int j = 0; j < 8; j++)
            crow[j] = acc[i][j] + bias[col0 + tx * 8 + j];
    }
}

// ---------------------------------------------------------------------------
// Flash attention (causal), fp32. One block handles (b, h, 64-query tile).
// Iterates over 64-key tiles with online softmax.
// Reads Q/K/V directly from the interleaved qkv buffer [B*T, 3*C].
// Writes attention output to g_attn laid out as [B*T, C] (head h at cols h*64).
// 256 threads; thread (tx,ty) in 16x16 owns a 4x4 fragment.
// ---------------------------------------------------------------------------
constexpr int SSTR = 66;   // padded stride for transposed [d][m] / [c][m] tiles
constexpr int VSTR = 64;   // V tile stride (row-major [c][d])
constexpr int FLASH_SMEM = (3 * 64 * SSTR + 64 * VSTR) * (int)sizeof(float);

__global__ __launch_bounds__(256)
void flash_attn_kernel(const float* __restrict__ qkv, float* __restrict__ out)
{
    extern __shared__ float smem[];
    float* Qs = smem;                  // [d][m], stride SSTR
    float* Ks = Qs + 64 * SSTR;        // [d][n], stride SSTR
    float* Ps = Ks + 64 * SSTR;        // [c][m], stride SSTR
    float* Vs = Ps + 64 * SSTR;        // [c][d], stride VSTR

    const int tid = threadIdx.x;
    const int tx = tid & 15;
    const int ty = tid >> 4;
    const int bh = blockIdx.y;
    const int b  = bh >> 4;
    const int h  = bh & 15;
    const int qblk = blockIdx.x;
    const int q0 = qblk * 64;
    const int rs = 3 * 1024;           // qkv row stride

    // ---- load Q tile transposed: Qs[d][t] ----
    const float* qb = qkv + (size_t)(b * 2048 + q0) * rs + h * 64;
#pragma unroll
    for (int it = 0; it < 4; it++) {
        int i = tid + it * 256;
        int t = i >> 4;
        int d = (i & 15) * 4;
        float4 v = *(const float4*)(qb + (size_t)t * rs + d);
        Qs[(d + 0) * SSTR + t] = v.x;
        Qs[(d + 1) * SSTR + t] = v.y;
        Qs[(d + 2) * SSTR + t] = v.z;
        Qs[(d + 3) * SSTR + t] = v.w;
    }

    float o[4][4];
    float mrow[4], lrow[4];
#pragma unroll
    for (int i = 0; i < 4; i++) {
        mrow[i] = -1e30f;
        lrow[i] = 0.0f;
#pragma unroll
        for (int j = 0; j < 4; j++) o[i][j] = 0.0f;
    }

    for (int kt = 0; kt <= qblk; kt++) {
        const float* kb = qkv + (size_t)(b * 2048 + kt * 64) * rs + 1024 + h * 64;
        const float* vb = kb + 1024;

        __syncthreads();   // previous iteration done reading Ks/Vs/Ps
        // ---- load K tile transposed Ks[d][t], V tile row-major Vs[t][d] ----
#pragma unroll
        for (int it = 0; it < 4; it++) {
            int i = tid + it * 256;
            int t = i >> 4;
            int d = (i & 15) * 4;
            float4 kv = *(const float4*)(kb + (size_t)t * rs + d);
            Ks[(d + 0) * SSTR + t] = kv.x;
            Ks[(d + 1) * SSTR + t] = kv.y;
            Ks[(d + 2) * SSTR + t] = kv.z;
            Ks[(d + 3) * SSTR + t] = kv.w;
            float4 vv = *(const float4*)(vb + (size_t)t * rs + d);
            *(float4*)&Vs[t * VSTR + d] = vv;
        }
        __syncthreads();

        // ---- S = Q K^T (64x64), fragment 4x4 per thread ----
        float s[4][4];
#pragma unroll
        for (int i = 0; i < 4; i++)
#pragma unroll
            for (int j = 0; j < 4; j++) s[i][j] = 0.0f;

#pragma unroll 4
        for (int k = 0; k < 64; k++) {
            float a[4], bb[4];
#pragma unroll
            for (int i = 0; i < 4; i++) a[i] = Qs[k * SSTR + ty * 4 + i];
#pragma unroll
            for (int j = 0; j < 4; j++) bb[j] = Ks[k * SSTR + tx * 4 + j];
#pragma unroll
            for (int i = 0; i < 4; i++)
#pragma unroll
                for (int j = 0; j < 4; j++)
                    s[i][j] += a[i] * bb[j];
        }

        // ---- scale + causal mask ----
        const float sc = 0.125f;  // 1/sqrt(64)
        if (kt == qblk) {
#pragma unroll
            for (int i = 0; i < 4; i++)
#pragma unroll
                for (int j = 0; j < 4; j++)
                    s[i][j] = (tx * 4 + j <= ty * 4 + i) ? s[i][j] * sc : -1e30f;
        } else {
#pragma unroll
            for (int i = 0; i < 4; i++)
#pragma unroll
                for (int j = 0; j < 4; j++)
                    s[i][j] *= sc;
        }

        // ---- online softmax (rows span 16 lanes sharing ty) ----
        float mloc[4], lloc[4];
#pragma unroll
        for (int i = 0; i < 4; i++) {
            mloc[i] = s[i][0];
#pragma unroll
            for (int j = 1; j < 4; j++) mloc[i] = fmaxf(mloc[i], s[i][j]);
        }
#pragma unroll
        for (int off = 8; off >= 1; off >>= 1)
#pragma unroll
            for (int i = 0; i < 4; i++)
                mloc[i] = fmaxf(mloc[i], __shfl_xor_sync(0xffffffffu, mloc[i], off));

#pragma unroll
        for (int i = 0; i < 4; i++) {
            float mn = fmaxf(mrow[i], mloc[i]);
            float corr = __expf(mrow[i] - mn);
            mrow[i] = mn;
            lloc[i] = 0.0f;
#pragma unroll
            for (int j = 0; j < 4; j++) {
                s[i][j] = __expf(s[i][j] - mn);   // s now holds P
                lloc[i] += s[i][j];
            }
#pragma unroll
            for (int j = 0; j < 4; j++) o[i][j] *= corr;
            lrow[i] *= corr;
        }
#pragma unroll
        for (int off = 8; off >= 1; off >>= 1)
#pragma unroll
            for (int i = 0; i < 4; i++)
                lloc[i] += __shfl_xor_sync(0xffffffffu, lloc[i], off);
#pragma unroll
        for (int i = 0; i < 4; i++) lrow[i] += lloc[i];

        // ---- stage P transposed: Ps[c][m] ----
#pragma unroll
        for (int i = 0; i < 4; i++)
#pragma unroll
            for (int j = 0; j < 4; j++)
                Ps[(tx * 4 + j) * SSTR + ty * 4 + i] = s[i][j];
        __syncthreads();

        // ---- O += P V ----
#pragma unroll 4
        for (int c = 0; c < 64; c++) {
            float a[4], bb[4];
#pragma unroll
            for (int i = 0; i < 4; i++) a[i] = Ps[c * SSTR + ty * 4 + i];
#pragma unroll
            for (int j = 0; j < 4; j++) bb[j] = Vs[c * VSTR + tx * 4 + j];
#pragma unroll
            for (int i = 0; i < 4; i++)
#pragma unroll
                for (int j = 0; j < 4; j++)
                    o[i][j] += a[i] * bb[j];
        }
    }

    // ---- epilogue: normalize and write [B*T, C] ----
#pragma unroll
    for (int i = 0; i < 4; i++) {
        float inv = 1.0f / lrow[i];
        float* orow = out + (size_t)(b * 2048 + q0 + ty * 4 + i) * 1024 + h * 64 + tx * 4;
#pragma unroll
        for (int j = 0; j < 4; j++)
            orow[j] = o[i][j] * inv;
    }
}

// ---------------------------------------------------------------------------
// kernel_launch: qkv gemm -> flash attention -> output gemm
// ---------------------------------------------------------------------------
extern "C" void kernel_launch(void* const* d_in, const int* in_sizes, int n_in,
                              void* d_out, int out_size)
{
    const float* x     = (const float*)d_in[0];   // [4096, 1024]
    const float* w_qkv = (const float*)d_in[1];   // [1024, 3072]
    const float* b_qkv = (const float*)d_in[2];   // [3072]
    const float* w_out = (const float*)d_in[3];   // [1024, 1024]
    const float* b_out = (const float*)d_in[4];   // [1024]
    float* out = (float*)d_out;                   // [4096, 1024]

    float* qkv = nullptr;
    float* attn = nullptr;
    cudaGetSymbolAddress((void**)&qkv,  g_qkv);
    cudaGetSymbolAddress((void**)&attn, g_attn);

    static bool attr_set = false;
    if (!attr_set) {
        cudaFuncSetAttribute(flash_attn_kernel,
                             cudaFuncAttributeMaxDynamicSharedMemorySize, FLASH_SMEM);
        attr_set = true;
    }

    // 1) QKV projection: [4096,1024] x [1024,3072] + b -> g_qkv
    {
        dim3 grid(3072 / 128, 4096 / 128);
        sgemm_bias_kernel<<<grid, 256>>>(x, w_qkv, b_qkv, qkv, 4096, 3072, 1024);
    }

    // 2) Causal flash attention -> g_attn [4096, 1024]
    {
        dim3 grid(2048 / 64, 2 * 16);   // (query tiles, B*H)
        flash_attn_kernel<<<grid, 256, FLASH_SMEM>>>(qkv, attn);
    }

    // 3) Output projection: [4096,1024] x [1024,1024] + b -> d_out
    {
        dim3 grid(1024 / 128, 4096 / 128);
        sgemm_bias_kernel<<<grid, 256>>>(attn, w_out, b_out, out, 4096, 1024, 1024);
    }
}

// round 7
// speedup vs baseline: 1.5729x; 1.5729x over previous
#include <cuda_runtime.h>
#include <cstdint>

// Problem constants: B=2, T=2048, C=1024, H=16, D=64
__device__ float g_qkv[4096 * 3072];
__device__ float g_attn[4096 * 1024];
__device__ float g_wt[3072 * 1024 + 1024 * 1024];   // W_qkv^T then W_out^T

// ---------------------------------------------------------------------------
// Transpose kernel: out[N,K] = in[K,N].
// ---------------------------------------------------------------------------
__global__ void transpose_kernel(const float* __restrict__ in, float* __restrict__ out,
                                 int R, int Ccols)
{
    __shared__ float tile[32][33];
    int c = blockIdx.x * 32 + threadIdx.x;
    int r0 = blockIdx.y * 32;
#pragma unroll
    for (int i = 0; i < 32; i += 8)
        tile[threadIdx.y + i][threadIdx.x] = in[(size_t)(r0 + threadIdx.y + i) * Ccols + c];
    __syncthreads();
    int oc = blockIdx.y * 32 + threadIdx.x;
    int or0 = blockIdx.x * 32;
#pragma unroll
    for (int i = 0; i < 32; i += 8)
        out[(size_t)(or0 + threadIdx.y + i) * R + oc] = tile[threadIdx.x][threadIdx.y + i];
}

// ---------------------------------------------------------------------------
// mma.sync tf32 GEMM: C[M,N] = A[M,K] * BT[N,K]^T + bias[N]
// A row-major [M,K], BT row-major [N,K]. M,N mult of 128, K mult of 32.
// CTA tile 128x128, 8 warps (2 along M x 4 along N), warp tile 64x32.
// K-chunk 32, double-buffered SMEM, register-staged global loads.
// ---------------------------------------------------------------------------
static __device__ __forceinline__ uint32_t f2tf32(float f) {
    uint32_t u;
    asm("cvt.rna.tf32.f32 %0, %1;" : "=r"(u) : "f"(f));
    return u;
}

static __device__ __forceinline__ void mma_tf32(
    float c[4], uint32_t a0, uint32_t a1, uint32_t a2, uint32_t a3,
    uint32_t b0, uint32_t b1)
{
    asm volatile(
        "mma.sync.aligned.m16n8k8.row.col.f32.tf32.tf32.f32 "
        "{%0,%1,%2,%3}, {%4,%5,%6,%7}, {%8,%9}, {%0,%1,%2,%3};"
        : "+f"(c[0]), "+f"(c[1]), "+f"(c[2]), "+f"(c[3])
        : "r"(a0), "r"(a1), "r"(a2), "r"(a3), "r"(b0), "r"(b1));
}

constexpr int ASTR = 36;                       // padded smem stride (floats)
constexpr int GEMM_SMEM = 2 * 2 * 128 * ASTR * (int)sizeof(float);  // 73728 B

__global__ __launch_bounds__(256)
void gemm_mma_kernel(const float* __restrict__ A, const float* __restrict__ BT,
                     const float* __restrict__ bias, float* __restrict__ C,
                     int M, int N, int K)
{
    extern __shared__ float sm[];
    // layout: As[2][128][ASTR], Bs[2][128][ASTR]  (As[buf][row=m][col=k], Bs[buf][row=n][col=k])
    float* AsBase = sm;
    float* BsBase = sm + 2 * 128 * ASTR;

    const int tid  = threadIdx.x;
    const int wid  = tid >> 5;
    const int lane = tid & 31;
    const int gid  = lane >> 2;          // 0..7
    const int tig  = lane & 3;           // 0..3
    const int warp_m = wid & 1;          // 0..1  (64 rows each)
    const int warp_n = wid >> 1;         // 0..3  (32 cols each)

    const int row0 = blockIdx.y * 128;
    const int n0   = blockIdx.x * 128;

    // global load mapping: per it (0..3): row = arow + it*32, 4 floats at acol
    const int arow = tid >> 3;           // 0..31
    const int acol = (tid & 7) * 4;      // 0..28
    const float* Ab = A  + (size_t)(row0 + arow) * K + acol;
    const float* Bb = BT + (size_t)(n0  + arow) * K + acol;

    float acc[4][4][4];
#pragma unroll
    for (int mi = 0; mi < 4; mi++)
#pragma unroll
        for (int ni = 0; ni < 4; ni++)
#pragma unroll
            for (int r = 0; r < 4; r++) acc[mi][ni][r] = 0.0f;

    const int nchunk = K / 32;

    // prologue: stage chunk 0 into buffer 0
    {
        float* As = AsBase;
        float* Bs = BsBase;
#pragma unroll
        for (int it = 0; it < 4; it++) {
            float4 va = *(const float4*)(Ab + (size_t)(it * 32) * K);
            float4 vb = *(const float4*)(Bb + (size_t)(it * 32) * K);
            float* ad = &As[(arow + it * 32) * ASTR + acol];
            float* bd = &Bs[(arow + it * 32) * ASTR + acol];
            ad[0] = __uint_as_float(f2tf32(va.x)); ad[1] = __uint_as_float(f2tf32(va.y));
            ad[2] = __uint_as_float(f2tf32(va.z)); ad[3] = __uint_as_float(f2tf32(va.w));
            bd[0] = __uint_as_float(f2tf32(vb.x)); bd[1] = __uint_as_float(f2tf32(vb.y));
            bd[2] = __uint_as_float(f2tf32(vb.z)); bd[3] = __uint_as_float(f2tf32(vb.w));
        }
    }
    __syncthreads();

    for (int c = 0; c < nchunk; c++) {
        const int buf = c & 1;
        const float* As = AsBase + buf * 128 * ASTR;
        const float* Bs = BsBase + buf * 128 * ASTR;

        // prefetch next chunk into registers (no stall until stores below)
        float4 pa[4], pb[4];
        const bool more = (c + 1 < nchunk);
        if (more) {
            const int k1 = (c + 1) * 32;
#pragma unroll
            for (int it = 0; it < 4; it++) {
                pa[it] = *(const float4*)(Ab + (size_t)(it * 32) * K + k1);
                pb[it] = *(const float4*)(Bb + (size_t)(it * 32) * K + k1);
            }
        }

        // compute on current buffer: 4 k-steps of 8
        const int mbase = warp_m * 64;
        const int nbase = warp_n * 32;
#pragma unroll
        for (int kk = 0; kk < 32; kk += 8) {
            uint32_t afr[4][4];
#pragma unroll
            for (int mi = 0; mi < 4; mi++) {
                const int r = mbase + mi * 16;
                afr[mi][0] = __float_as_uint(As[(r + gid)     * ASTR + kk + tig]);
                afr[mi][1] = __float_as_uint(As[(r + gid + 8) * ASTR + kk + tig]);
                afr[mi][2] = __float_as_uint(As[(r + gid)     * ASTR + kk + tig + 4]);
                afr[mi][3] = __float_as_uint(As[(r + gid + 8) * ASTR + kk + tig + 4]);
            }
            uint32_t bfr[4][2];
#pragma unroll
            for (int ni = 0; ni < 4; ni++) {
                const int n = nbase + ni * 8 + gid;
                bfr[ni][0] = __float_as_uint(Bs[n * ASTR + kk + tig]);
                bfr[ni][1] = __float_as_uint(Bs[n * ASTR + kk + tig + 4]);
            }
#pragma unroll
            for (int mi = 0; mi < 4; mi++)
#pragma unroll
                for (int ni = 0; ni < 4; ni++)
                    mma_tf32(acc[mi][ni], afr[mi][0], afr[mi][1], afr[mi][2], afr[mi][3],
                             bfr[ni][0], bfr[ni][1]);
        }

        if (more) {
            // store prefetched chunk to the other buffer (safe: all threads
            // finished computing on it before the previous __syncthreads)
            float* Asn = AsBase + ((c + 1) & 1) * 128 * ASTR;
            float* Bsn = BsBase + ((c + 1) & 1) * 128 * ASTR;
#pragma unroll
            for (int it = 0; it < 4; it++) {
                float* ad = &Asn[(arow + it * 32) * ASTR + acol];
                float* bd = &Bsn[(arow + it * 32) * ASTR + acol];
                ad[0] = __uint_as_float(f2tf32(pa[it].x)); ad[1] = __uint_as_float(f2tf32(pa[it].y));
                ad[2] = __uint_as_float(f2tf32(pa[it].z)); ad[3] = __uint_as_float(f2tf32(pa[it].w));
                bd[0] = __uint_as_float(f2tf32(pb[it].x)); bd[1] = __uint_as_float(f2tf32(pb[it].y));
                bd[2] = __uint_as_float(f2tf32(pb[it].z)); bd[3] = __uint_as_float(f2tf32(pb[it].w));
            }
            __syncthreads();
        }
    }

    // epilogue: write C fragments + bias. c0:(gid, 2t) c1:(gid, 2t+1) c2:(gid+8, 2t) c3:(gid+8, 2t+1)
#pragma unroll
    for (int mi = 0; mi < 4; mi++) {
        const int r = row0 + warp_m * 64 + mi * 16 + gid;
#pragma unroll
        for (int ni = 0; ni < 4; ni++) {
            const int cc = n0 + warp_n * 32 + ni * 8 + tig * 2;
            const float b0 = bias[cc], b1 = bias[cc + 1];
            float2 v0 = { acc[mi][ni][0] + b0, acc[mi][ni][1] + b1 };
            float2 v1 = { acc[mi][ni][2] + b0, acc[mi][ni][3] + b1 };
            *(float2*)(C + (size_t)r * N + cc)       = v0;
            *(float2*)(C + (size_t)(r + 8) * N + cc) = v1;
        }
    }
}

// ---------------------------------------------------------------------------
// Flash attention (causal), fp32 FFMA (unchanged — R7 target).
// ---------------------------------------------------------------------------
constexpr int SSTR = 66;
constexpr int VSTR = 64;
constexpr int FLASH_SMEM = (3 * 64 * SSTR + 64 * VSTR) * (int)sizeof(float);

__global__ __launch_bounds__(256)
void flash_attn_kernel(const float* __restrict__ qkv, float* __restrict__ out)
{
    extern __shared__ float smem[];
    float* Qs = smem;
    float* Ks = Qs + 64 * SSTR;
    float* Ps = Ks + 64 * SSTR;
    float* Vs = Ps + 64 * SSTR;

    const int tid = threadIdx.x;
    const int tx = tid & 15;
    const int ty = tid >> 4;
    const int bh = blockIdx.y;
    const int b  = bh >> 4;
    const int h  = bh & 15;
    const int qblk = blockIdx.x;
    const int q0 = qblk * 64;
    const int rs = 3 * 1024;

    const float* qb = qkv + (size_t)(b * 2048 + q0) * rs + h * 64;
#pragma unroll
    for (int it = 0; it < 4; it++) {
        int i = tid + it * 256;
        int t = i >> 4;
        int d = (i & 15) * 4;
        float4 v = *(const float4*)(qb + (size_t)t * rs + d);
        Qs[(d + 0) * SSTR + t] = v.x;
        Qs[(d + 1) * SSTR + t] = v.y;
        Qs[(d + 2) * SSTR + t] = v.z;
        Qs[(d + 3) * SSTR + t] = v.w;
    }

    float o[4][4];
    float mrow[4], lrow[4];
#pragma unroll
    for (int i = 0; i < 4; i++) {
        mrow[i] = -1e30f;
        lrow[i] = 0.0f;
#pragma unroll
        for (int j = 0; j < 4; j++) o[i][j] = 0.0f;
    }

    for (int kt = 0; kt <= qblk; kt++) {
        const float* kb = qkv + (size_t)(b * 2048 + kt * 64) * rs + 1024 + h * 64;
        const float* vb = kb + 1024;

        __syncthreads();
#pragma unroll
        for (int it = 0; it < 4; it++) {
            int i = tid + it * 256;
            int t = i >> 4;
            int d = (i & 15) * 4;
            float4 kv = *(const float4*)(kb + (size_t)t * rs + d);
            Ks[(d + 0) * SSTR + t] = kv.x;
            Ks[(d + 1) * SSTR + t] = kv.y;
            Ks[(d + 2) * SSTR + t] = kv.z;
            Ks[(d + 3) * SSTR + t] = kv.w;
            float4 vv = *(const float4*)(vb + (size_t)t * rs + d);
            *(float4*)&Vs[t * VSTR + d] = vv;
        }
        __syncthreads();

        float s[4][4];
#pragma unroll
        for (int i = 0; i < 4; i++)
#pragma unroll
            for (int j = 0; j < 4; j++) s[i][j] = 0.0f;

#pragma unroll 4
        for (int k = 0; k < 64; k++) {
            float a[4], bb[4];
#pragma unroll
            for (int i = 0; i < 4; i++) a[i] = Qs[k * SSTR + ty * 4 + i];
#pragma unroll
            for (int j = 0; j < 4; j++) bb[j] = Ks[k * SSTR + tx * 4 + j];
#pragma unroll
            for (int i = 0; i < 4; i++)
#pragma unroll
                for (int j = 0; j < 4; j++)
                    s[i][j] += a[i] * bb[j];
        }

        const float sc = 0.125f;
        if (kt == qblk) {
#pragma unroll
            for (int i = 0; i < 4; i++)
#pragma unroll
                for (int j = 0; j < 4; j++)
                    s[i][j] = (tx * 4 + j <= ty * 4 + i) ? s[i][j] * sc : -1e30f;
        } else {
#pragma unroll
            for (int i = 0; i < 4; i++)
#pragma unroll
                for (int j = 0; j < 4; j++)
                    s[i][j] *= sc;
        }

        float mloc[4], lloc[4];
#pragma unroll
        for (int i = 0; i < 4; i++) {
            mloc[i] = s[i][0];
#pragma unroll
            for (int j = 1; j < 4; j++) mloc[i] = fmaxf(mloc[i], s[i][j]);
        }
#pragma unroll
        for (int off = 8; off >= 1; off >>= 1)
#pragma unroll
            for (int i = 0; i < 4; i++)
                mloc[i] = fmaxf(mloc[i], __shfl_xor_sync(0xffffffffu, mloc[i], off));

#pragma unroll
        for (int i = 0; i < 4; i++) {
            float mn = fmaxf(mrow[i], mloc[i]);
            float corr = __expf(mrow[i] - mn);
            mrow[i] = mn;
            lloc[i] = 0.0f;
#pragma unroll
            for (int j = 0; j < 4; j++) {
                s[i][j] = __expf(s[i][j] - mn);
                lloc[i] += s[i][j];
            }
#pragma unroll
            for (int j = 0; j < 4; j++) o[i][j] *= corr;
            lrow[i] *= corr;
        }
#pragma unroll
        for (int off = 8; off >= 1; off >>= 1)
#pragma unroll
            for (int i = 0; i < 4; i++)
                lloc[i] += __shfl_xor_sync(0xffffffffu, lloc[i], off);
#pragma unroll
        for (int i = 0; i < 4; i++) lrow[i] += lloc[i];

#pragma unroll
        for (int i = 0; i < 4; i++)
#pragma unroll
            for (int j = 0; j < 4; j++)
                Ps[(tx * 4 + j) * SSTR + ty * 4 + i] = s[i][j];
        __syncthreads();

#pragma unroll 4
        for (int c = 0; c < 64; c++) {
            float a[4], bb[4];
#pragma unroll
            for (int i = 0; i < 4; i++) a[i] = Ps[c * SSTR + ty * 4 + i];
#pragma unroll
            for (int j = 0; j < 4; j++) bb[j] = Vs[c * VSTR + tx * 4 + j];
#pragma unroll
            for (int i = 0; i < 4; i++)
#pragma unroll
                for (int j = 0; j < 4; j++)
                    o[i][j] += a[i] * bb[j];
        }
    }

#pragma unroll
    for (int i = 0; i < 4; i++) {
        float inv = 1.0f / lrow[i];
        float* orow = out + (size_t)(b * 2048 + q0 + ty * 4 + i) * 1024 + h * 64 + tx * 4;
#pragma unroll
        for (int j = 0; j < 4; j++)
            orow[j] = o[i][j] * inv;
    }
}

// ---------------------------------------------------------------------------
// kernel_launch
// ---------------------------------------------------------------------------
extern "C" void kernel_launch(void* const* d_in, const int* in_sizes, int n_in,
                              void* d_out, int out_size)
{
    const float* x     = (const float*)d_in[0];   // [4096, 1024]
    const float* w_qkv = (const float*)d_in[1];   // [1024, 3072]
    const float* b_qkv = (const float*)d_in[2];   // [3072]
    const float* w_out = (const float*)d_in[3];   // [1024, 1024]
    const float* b_out = (const float*)d_in[4];   // [1024]
    float* out = (float*)d_out;                   // [4096, 1024]

    float *qkv = nullptr, *attn = nullptr, *wt = nullptr;
    cudaGetSymbolAddress((void**)&qkv,  g_qkv);
    cudaGetSymbolAddress((void**)&attn, g_attn);
    cudaGetSymbolAddress((void**)&wt,   g_wt);
    float* wt_qkv = wt;                      // [3072, 1024]
    float* wt_out = wt + 3072 * 1024;        // [1024, 1024]

    cudaFuncSetAttribute(gemm_mma_kernel,
                         cudaFuncAttributeMaxDynamicSharedMemorySize, GEMM_SMEM);
    cudaFuncSetAttribute(flash_attn_kernel,
                         cudaFuncAttributeMaxDynamicSharedMemorySize, FLASH_SMEM);

    // 0) transpose weights
    {
        dim3 blk(32, 8);
        transpose_kernel<<<dim3(3072 / 32, 1024 / 32), blk>>>(w_qkv, wt_qkv, 1024, 3072);
        transpose_kernel<<<dim3(1024 / 32, 1024 / 32), blk>>>(w_out, wt_out, 1024, 1024);
    }

    // 1) QKV projection (mma.sync tf32): [4096,1024] x [1024,3072] + b
    {
        dim3 grid(3072 / 128, 4096 / 128);
        gemm_mma_kernel<<<grid, 256, GEMM_SMEM>>>(x, wt_qkv, b_qkv, qkv, 4096, 3072, 1024);
    }

    // 2) Causal flash attention -> g_attn [4096, 1024]
    {
        dim3 grid(2048 / 64, 2 * 16);
        flash_attn_kernel<<<grid, 256, FLASH_SMEM>>>(qkv, attn);
    }

    // 3) Output projection (mma.sync tf32): [4096,1024] x [1024,1024] + b
    {
        dim3 grid(1024 / 128, 4096 / 128);
        gemm_mma_kernel<<<grid, 256, GEMM_SMEM>>>(attn, wt_out, b_out, out, 4096, 1024, 1024);
    }
}

// round 8
// speedup vs baseline: 2.7277x; 1.7342x over previous
#include <cuda_runtime.h>
#include <cstdint>

// Problem constants: B=2, T=2048, C=1024, H=16, D=64
__device__ float g_qkv[4096 * 3072];
__device__ float g_attn[4096 * 1024];
__device__ float g_wt[3072 * 1024 + 1024 * 1024];   // W_qkv^T then W_out^T

// ---------------------------------------------------------------------------
// helpers
// ---------------------------------------------------------------------------
static __device__ __forceinline__ uint32_t f2tf32(float f) {
    uint32_t u;
    asm("cvt.rna.tf32.f32 %0, %1;" : "=r"(u) : "f"(f));
    return u;
}
static __device__ __forceinline__ float tf32r(float f) {
    return __uint_as_float(f2tf32(f));
}
static __device__ __forceinline__ void mma_tf32(
    float c[4], uint32_t a0, uint32_t a1, uint32_t a2, uint32_t a3,
    uint32_t b0, uint32_t b1)
{
    asm volatile(
        "mma.sync.aligned.m16n8k8.row.col.f32.tf32.tf32.f32 "
        "{%0,%1,%2,%3}, {%4,%5,%6,%7}, {%8,%9}, {%0,%1,%2,%3};"
        : "+f"(c[0]), "+f"(c[1]), "+f"(c[2]), "+f"(c[3])
        : "r"(a0), "r"(a1), "r"(a2), "r"(a3), "r"(b0), "r"(b1));
}

// ---------------------------------------------------------------------------
// Transpose kernel: out[N,K] = in[K,N].
// ---------------------------------------------------------------------------
__global__ void transpose_kernel(const float* __restrict__ in, float* __restrict__ out,
                                 int R, int Ccols)
{
    __shared__ float tile[32][33];
    int c = blockIdx.x * 32 + threadIdx.x;
    int r0 = blockIdx.y * 32;
#pragma unroll
    for (int i = 0; i < 32; i += 8)
        tile[threadIdx.y + i][threadIdx.x] = in[(size_t)(r0 + threadIdx.y + i) * Ccols + c];
    __syncthreads();
    int oc = blockIdx.y * 32 + threadIdx.x;
    int or0 = blockIdx.x * 32;
#pragma unroll
    for (int i = 0; i < 32; i += 8)
        out[(size_t)(or0 + threadIdx.y + i) * R + oc] = tile[threadIdx.x][threadIdx.y + i];
}

// ---------------------------------------------------------------------------
// mma.sync tf32 GEMM (unchanged from R7): C = A * BT^T + bias
// ---------------------------------------------------------------------------
constexpr int ASTR = 36;
constexpr int GEMM_SMEM = 2 * 2 * 128 * ASTR * (int)sizeof(float);

__global__ __launch_bounds__(256)
void gemm_mma_kernel(const float* __restrict__ A, const float* __restrict__ BT,
                     const float* __restrict__ bias, float* __restrict__ C,
                     int M, int N, int K)
{
    extern __shared__ float sm[];
    float* AsBase = sm;
    float* BsBase = sm + 2 * 128 * ASTR;

    const int tid  = threadIdx.x;
    const int wid  = tid >> 5;
    const int lane = tid & 31;
    const int gid  = lane >> 2;
    const int tig  = lane & 3;
    const int warp_m = wid & 1;
    const int warp_n = wid >> 1;

    const int row0 = blockIdx.y * 128;
    const int n0   = blockIdx.x * 128;

    const int arow = tid >> 3;
    const int acol = (tid & 7) * 4;
    const float* Ab = A  + (size_t)(row0 + arow) * K + acol;
    const float* Bb = BT + (size_t)(n0  + arow) * K + acol;

    float acc[4][4][4];
#pragma unroll
    for (int mi = 0; mi < 4; mi++)
#pragma unroll
        for (int ni = 0; ni < 4; ni++)
#pragma unroll
            for (int r = 0; r < 4; r++) acc[mi][ni][r] = 0.0f;

    const int nchunk = K / 32;

    {
        float* As = AsBase;
        float* Bs = BsBase;
#pragma unroll
        for (int it = 0; it < 4; it++) {
            float4 va = *(const float4*)(Ab + (size_t)(it * 32) * K);
            float4 vb = *(const float4*)(Bb + (size_t)(it * 32) * K);
            float* ad = &As[(arow + it * 32) * ASTR + acol];
            float* bd = &Bs[(arow + it * 32) * ASTR + acol];
            ad[0] = tf32r(va.x); ad[1] = tf32r(va.y); ad[2] = tf32r(va.z); ad[3] = tf32r(va.w);
            bd[0] = tf32r(vb.x); bd[1] = tf32r(vb.y); bd[2] = tf32r(vb.z); bd[3] = tf32r(vb.w);
        }
    }
    __syncthreads();

    for (int c = 0; c < nchunk; c++) {
        const int buf = c & 1;
        const float* As = AsBase + buf * 128 * ASTR;
        const float* Bs = BsBase + buf * 128 * ASTR;

        float4 pa[4], pb[4];
        const bool more = (c + 1 < nchunk);
        if (more) {
            const int k1 = (c + 1) * 32;
#pragma unroll
            for (int it = 0; it < 4; it++) {
                pa[it] = *(const float4*)(Ab + (size_t)(it * 32) * K + k1);
                pb[it] = *(const float4*)(Bb + (size_t)(it * 32) * K + k1);
            }
        }

        const int mbase = warp_m * 64;
        const int nbase = warp_n * 32;
#pragma unroll
        for (int kk = 0; kk < 32; kk += 8) {
            uint32_t afr[4][4];
#pragma unroll
            for (int mi = 0; mi < 4; mi++) {
                const int r = mbase + mi * 16;
                afr[mi][0] = __float_as_uint(As[(r + gid)     * ASTR + kk + tig]);
                afr[mi][1] = __float_as_uint(As[(r + gid + 8) * ASTR + kk + tig]);
                afr[mi][2] = __float_as_uint(As[(r + gid)     * ASTR + kk + tig + 4]);
                afr[mi][3] = __float_as_uint(As[(r + gid + 8) * ASTR + kk + tig + 4]);
            }
            uint32_t bfr[4][2];
#pragma unroll
            for (int ni = 0; ni < 4; ni++) {
                const int n = nbase + ni * 8 + gid;
                bfr[ni][0] = __float_as_uint(Bs[n * ASTR + kk + tig]);
                bfr[ni][1] = __float_as_uint(Bs[n * ASTR + kk + tig + 4]);
            }
#pragma unroll
            for (int mi = 0; mi < 4; mi++)
#pragma unroll
                for (int ni = 0; ni < 4; ni++)
                    mma_tf32(acc[mi][ni], afr[mi][0], afr[mi][1], afr[mi][2], afr[mi][3],
                             bfr[ni][0], bfr[ni][1]);
        }

        if (more) {
            float* Asn = AsBase + ((c + 1) & 1) * 128 * ASTR;
            float* Bsn = BsBase + ((c + 1) & 1) * 128 * ASTR;
#pragma unroll
            for (int it = 0; it < 4; it++) {
                float* ad = &Asn[(arow + it * 32) * ASTR + acol];
                float* bd = &Bsn[(arow + it * 32) * ASTR + acol];
                ad[0] = tf32r(pa[it].x); ad[1] = tf32r(pa[it].y);
                ad[2] = tf32r(pa[it].z); ad[3] = tf32r(pa[it].w);
                bd[0] = tf32r(pb[it].x); bd[1] = tf32r(pb[it].y);
                bd[2] = tf32r(pb[it].z); bd[3] = tf32r(pb[it].w);
            }
            __syncthreads();
        }
    }

#pragma unroll
    for (int mi = 0; mi < 4; mi++) {
        const int r = row0 + warp_m * 64 + mi * 16 + gid;
#pragma unroll
        for (int ni = 0; ni < 4; ni++) {
            const int cc = n0 + warp_n * 32 + ni * 8 + tig * 2;
            const float b0 = bias[cc], b1 = bias[cc + 1];
            float2 v0 = { acc[mi][ni][0] + b0, acc[mi][ni][1] + b1 };
            float2 v1 = { acc[mi][ni][2] + b0, acc[mi][ni][3] + b1 };
            *(float2*)(C + (size_t)r * N + cc)       = v0;
            *(float2*)(C + (size_t)(r + 8) * N + cc) = v1;
        }
    }
}

// ---------------------------------------------------------------------------
// Flash attention (causal) with mma.sync tf32.
// One CTA = (b, h, 128-row Q tile). 8 warps, each owns a 16-row strip.
// Q fragments register-resident (pre-scaled by 1/8). Per 64-key tile:
// S = Q K^T via mma, online softmax (quad shuffles), P staged via SMEM,
// O += P V via mma (V stored transposed [d][key]).
// ---------------------------------------------------------------------------
constexpr int KSTR = 68;
constexpr int FL2_SMEM = (64 * KSTR + 64 * KSTR + 128 * KSTR) * (int)sizeof(float); // 69632

__global__ __launch_bounds__(256, 2)
void flash_mma_kernel(const float* __restrict__ qkv, float* __restrict__ out)
{
    extern __shared__ float sm[];
    float* Ks  = sm;                    // [64][KSTR]  K[key][d] (tf32)
    float* Vst = sm + 64 * KSTR;        // [64][KSTR]  V^T[d][key] (tf32)
    float* Ps  = sm + 128 * KSTR;       // [128][KSTR] staging (Q then P)

    const int tid  = threadIdx.x;
    const int wid  = tid >> 5;
    const int lane = tid & 31;
    const int gid  = lane >> 2;
    const int tig  = lane & 3;

    const int qx = 15 - blockIdx.x;     // heavy tiles first
    const int bh = blockIdx.y;
    const int b  = bh >> 4;
    const int h  = bh & 15;
    const int q0 = qx * 128;
    const int rs = 3072;
    const float* base = qkv + (size_t)(b * 2048) * rs + h * 64;

    // ---- stage Q tile (scaled by 1/8, tf32) into Ps, then load fragments ----
#pragma unroll
    for (int i = 0; i < 8; i++) {
        int idx = tid + i * 256;
        int row = idx >> 4;
        int dg  = (idx & 15) * 4;
        float4 v = *(const float4*)(base + (size_t)(q0 + row) * rs + dg);
        float* d = &Ps[row * KSTR + dg];
        d[0] = tf32r(v.x * 0.125f); d[1] = tf32r(v.y * 0.125f);
        d[2] = tf32r(v.z * 0.125f); d[3] = tf32r(v.w * 0.125f);
    }
    __syncthreads();

    const int lr0 = wid * 16 + gid;     // local rows this thread owns
    const int lr1 = lr0 + 8;
    uint32_t qf[8][4];
#pragma unroll
    for (int kk = 0; kk < 8; kk++) {
        qf[kk][0] = __float_as_uint(Ps[lr0 * KSTR + kk * 8 + tig]);
        qf[kk][1] = __float_as_uint(Ps[lr1 * KSTR + kk * 8 + tig]);
        qf[kk][2] = __float_as_uint(Ps[lr0 * KSTR + kk * 8 + tig + 4]);
        qf[kk][3] = __float_as_uint(Ps[lr1 * KSTR + kk * 8 + tig + 4]);
    }

    float of[8][4];
#pragma unroll
    for (int ni = 0; ni < 8; ni++)
#pragma unroll
        for (int r = 0; r < 4; r++) of[ni][r] = 0.0f;
    float m0 = -1e30f, m1 = -1e30f, l0 = 0.0f, l1 = 0.0f;

    const int row0g = q0 + lr0;         // global rows
    const int row1g = row0g + 8;
    const int key   = tid >> 2;         // cooperative K/V load: one key/thread
    const int dbase = (tid & 3) * 16;
    const int nkt   = 2 * qx + 2;

    for (int kt = 0; kt < nkt; kt++) {
        __syncthreads();   // prior iteration done reading Ks/Vst/Ps
        // ---- load K tile -> Ks[key][d], V tile -> Vst[d][key] (tf32) ----
        {
            const float* krow = base + (size_t)(kt * 64 + key) * rs + 1024 + dbase;
            const float* vrow = krow + 1024;
#pragma unroll
            for (int i = 0; i < 4; i++) {
                float4 kv = *(const float4*)(krow + i * 4);
                float* kd = &Ks[key * KSTR + dbase + i * 4];
                kd[0] = tf32r(kv.x); kd[1] = tf32r(kv.y);
                kd[2] = tf32r(kv.z); kd[3] = tf32r(kv.w);
                float4 vv = *(const float4*)(vrow + i * 4);
                Vst[(dbase + i * 4 + 0) * KSTR + key] = tf32r(vv.x);
                Vst[(dbase + i * 4 + 1) * KSTR + key] = tf32r(vv.y);
                Vst[(dbase + i * 4 + 2) * KSTR + key] = tf32r(vv.z);
                Vst[(dbase + i * 4 + 3) * KSTR + key] = tf32r(vv.w);
            }
        }
        __syncthreads();

        // ---- S = Q K^T ----
        float sf[8][4];
#pragma unroll
        for (int ni = 0; ni < 8; ni++)
#pragma unroll
            for (int r = 0; r < 4; r++) sf[ni][r] = 0.0f;

#pragma unroll
        for (int kk = 0; kk < 8; kk++) {
            uint32_t bfr[8][2];
#pragma unroll
            for (int ni = 0; ni < 8; ni++) {
                bfr[ni][0] = __float_as_uint(Ks[(ni * 8 + gid) * KSTR + kk * 8 + tig]);
                bfr[ni][1] = __float_as_uint(Ks[(ni * 8 + gid) * KSTR + kk * 8 + tig + 4]);
            }
#pragma unroll
            for (int ni = 0; ni < 8; ni++)
                mma_tf32(sf[ni], qf[kk][0], qf[kk][1], qf[kk][2], qf[kk][3],
                         bfr[ni][0], bfr[ni][1]);
        }

        // ---- causal mask (only diagonal tiles) ----
        if (kt >= 2 * qx) {
            const int cb = kt * 64 + tig * 2;
#pragma unroll
            for (int ni = 0; ni < 8; ni++) {
                const int c0 = cb + ni * 8, c1 = c0 + 1;
                if (c0 > row0g) sf[ni][0] = -1e30f;
                if (c1 > row0g) sf[ni][1] = -1e30f;
                if (c0 > row1g) sf[ni][2] = -1e30f;
                if (c1 > row1g) sf[ni][3] = -1e30f;
            }
        }

        // ---- online softmax ----
        float mx0 = -1e30f, mx1 = -1e30f;
#pragma unroll
        for (int ni = 0; ni < 8; ni++) {
            mx0 = fmaxf(mx0, fmaxf(sf[ni][0], sf[ni][1]));
            mx1 = fmaxf(mx1, fmaxf(sf[ni][2], sf[ni][3]));
        }
        mx0 = fmaxf(mx0, __shfl_xor_sync(0xffffffffu, mx0, 1));
        mx0 = fmaxf(mx0, __shfl_xor_sync(0xffffffffu, mx0, 2));
        mx1 = fmaxf(mx1, __shfl_xor_sync(0xffffffffu, mx1, 1));
        mx1 = fmaxf(mx1, __shfl_xor_sync(0xffffffffu, mx1, 2));

        const float mn0 = fmaxf(m0, mx0);
        const float mn1 = fmaxf(m1, mx1);
        const float corr0 = __expf(m0 - mn0);
        const float corr1 = __expf(m1 - mn1);
        m0 = mn0; m1 = mn1;

        float ls0 = 0.0f, ls1 = 0.0f;
#pragma unroll
        for (int ni = 0; ni < 8; ni++) {
            sf[ni][0] = __expf(sf[ni][0] - mn0); ls0 += sf[ni][0];
            sf[ni][1] = __expf(sf[ni][1] - mn0); ls0 += sf[ni][1];
            sf[ni][2] = __expf(sf[ni][2] - mn1); ls1 += sf[ni][2];
            sf[ni][3] = __expf(sf[ni][3] - mn1); ls1 += sf[ni][3];
        }
        ls0 += __shfl_xor_sync(0xffffffffu, ls0, 1);
        ls0 += __shfl_xor_sync(0xffffffffu, ls0, 2);
        ls1 += __shfl_xor_sync(0xffffffffu, ls1, 1);
        ls1 += __shfl_xor_sync(0xffffffffu, ls1, 2);
        l0 = l0 * corr0 + ls0;
        l1 = l1 * corr1 + ls1;

#pragma unroll
        for (int ni = 0; ni < 8; ni++) {
            of[ni][0] *= corr0; of[ni][1] *= corr0;
            of[ni][2] *= corr1; of[ni][3] *= corr1;
        }

        // ---- stage P (tf32) for A-operand re-fragmentation ----
#pragma unroll
        for (int ni = 0; ni < 8; ni++) {
            float2 p0 = { tf32r(sf[ni][0]), tf32r(sf[ni][1]) };
            float2 p1 = { tf32r(sf[ni][2]), tf32r(sf[ni][3]) };
            *(float2*)&Ps[lr0 * KSTR + ni * 8 + tig * 2] = p0;
            *(float2*)&Ps[lr1 * KSTR + ni * 8 + tig * 2] = p1;
        }
        __syncthreads();

        // ---- O += P V ----
#pragma unroll
        for (int kk = 0; kk < 8; kk++) {
            uint32_t pa0 = __float_as_uint(Ps[lr0 * KSTR + kk * 8 + tig]);
            uint32_t pa1 = __float_as_uint(Ps[lr1 * KSTR + kk * 8 + tig]);
            uint32_t pa2 = __float_as_uint(Ps[lr0 * KSTR + kk * 8 + tig + 4]);
            uint32_t pa3 = __float_as_uint(Ps[lr1 * KSTR + kk * 8 + tig + 4]);
#pragma unroll
            for (int ni = 0; ni < 8; ni++) {
                uint32_t b0 = __float_as_uint(Vst[(ni * 8 + gid) * KSTR + kk * 8 + tig]);
                uint32_t b1 = __float_as_uint(Vst[(ni * 8 + gid) * KSTR + kk * 8 + tig + 4]);
                mma_tf32(of[ni], pa0, pa1, pa2, pa3, b0, b1);
            }
        }
    }

    // ---- epilogue ----
    const float inv0 = 1.0f / l0;
    const float inv1 = 1.0f / l1;
    float* o0 = out + (size_t)(b * 2048 + row0g) * 1024 + h * 64;
    float* o1 = o0 + (size_t)8 * 1024;
#pragma unroll
    for (int ni = 0; ni < 8; ni++) {
        float2 v0 = { of[ni][0] * inv0, of[ni][1] * inv0 };
        float2 v1 = { of[ni][2] * inv1, of[ni][3] * inv1 };
        *(float2*)(o0 + ni * 8 + tig * 2) = v0;
        *(float2*)(o1 + ni * 8 + tig * 2) = v1;
    }
}

// ---------------------------------------------------------------------------
// kernel_launch
// ---------------------------------------------------------------------------
extern "C" void kernel_launch(void* const* d_in, const int* in_sizes, int n_in,
                              void* d_out, int out_size)
{
    const float* x     = (const float*)d_in[0];   // [4096, 1024]
    const float* w_qkv = (const float*)d_in[1];   // [1024, 3072]
    const float* b_qkv = (const float*)d_in[2];   // [3072]
    const float* w_out = (const float*)d_in[3];   // [1024, 1024]
    const float* b_out = (const float*)d_in[4];   // [1024]
    float* out = (float*)d_out;                   // [4096, 1024]

    float *qkv = nullptr, *attn = nullptr, *wt = nullptr;
    cudaGetSymbolAddress((void**)&qkv,  g_qkv);
    cudaGetSymbolAddress((void**)&attn, g_attn);
    cudaGetSymbolAddress((void**)&wt,   g_wt);
    float* wt_qkv = wt;                      // [3072, 1024]
    float* wt_out = wt + 3072 * 1024;        // [1024, 1024]

    cudaFuncSetAttribute(gemm_mma_kernel,
                         cudaFuncAttributeMaxDynamicSharedMemorySize, GEMM_SMEM);
    cudaFuncSetAttribute(flash_mma_kernel,
                         cudaFuncAttributeMaxDynamicSharedMemorySize, FL2_SMEM);

    // 0) transpose weights
    {
        dim3 blk(32, 8);
        transpose_kernel<<<dim3(3072 / 32, 1024 / 32), blk>>>(w_qkv, wt_qkv, 1024, 3072);
        transpose_kernel<<<dim3(1024 / 32, 1024 / 32), blk>>>(w_out, wt_out, 1024, 1024);
    }

    // 1) QKV projection (mma.sync tf32)
    {
        dim3 grid(3072 / 128, 4096 / 128);
        gemm_mma_kernel<<<grid, 256, GEMM_SMEM>>>(x, wt_qkv, b_qkv, qkv, 4096, 3072, 1024);
    }

    // 2) Causal flash attention (mma.sync tf32) -> g_attn
    {
        dim3 grid(16, 2 * 16);   // (q tiles of 128, B*H)
        flash_mma_kernel<<<grid, 256, FL2_SMEM>>>(qkv, attn);
    }

    // 3) Output projection (mma.sync tf32)
    {
        dim3 grid(1024 / 128, 4096 / 128);
        gemm_mma_kernel<<<grid, 256, GEMM_SMEM>>>(attn, wt_out, b_out, out, 4096, 1024, 1024);
    }
}